// round 13
// baseline (speedup 1.0000x reference)
#include <cuda_runtime.h>
#include <cuda_bf16.h>
#include <cstdint>

// ---------------- problem constants ----------------
constexpr int Bc = 4, Sc = 4096, Dc = 1024;
constexpr int MTOT = Bc * Sc;   // 16384 rows
constexpr int Kc = 1024, Nc = 1024;
constexpr int NCHUNK = 16;      // K chunks of 64
constexpr int STAGE = 65536;    // {Ah 16K, Al 16K, Bh 16K, Bl 16K}
constexpr int SMEM_BYTES = 2 * STAGE;  // 128 KB double buffer

// ---------------- device scratch (no allocations allowed) ----------------
__device__ float g_q[(size_t)MTOT * Dc];
__device__ float g_k[(size_t)MTOT * Dc];
__device__ float g_v[(size_t)MTOT * Dc];
__device__ __nv_bfloat16 g_xh[(size_t)MTOT * Dc];   // split input x
__device__ __nv_bfloat16 g_xl[(size_t)MTOT * Dc];
__device__ __nv_bfloat16 g_aoh[(size_t)MTOT * Dc];  // split attn output
__device__ __nv_bfloat16 g_aol[(size_t)MTOT * Dc];
__device__ __nv_bfloat16 g_hh[(size_t)MTOT * Dc];   // split hidden (post-ReLU)
__device__ __nv_bfloat16 g_hl[(size_t)MTOT * Dc];
__device__ __nv_bfloat16 g_wh[5u * 1024 * 1024];    // transposed weights, hi
__device__ __nv_bfloat16 g_wl[5u * 1024 * 1024];    // transposed weights, lo
__device__ float g_awf[(size_t)MTOT * 64];          // attn_weights fallback sink

// ---------------- portable PTX helpers (NO 'a'-gated instructions) ----------------
#define DEVFN __device__ __forceinline__

DEVFN unsigned smem_u32(const void* p) {
    unsigned a;
    asm("{ .reg .u64 t; cvta.to.shared.u64 t, %1; cvt.u32.u64 %0, t; }" : "=r"(a) : "l"(p));
    return a;
}

#define CP16(dst, src)                                                       \
    asm volatile("cp.async.cg.shared.global [%0], [%1], 16;" ::"r"(dst),     \
                 "l"(src) : "memory")

DEVFN void cpcommit() { asm volatile("cp.async.commit_group;" ::: "memory"); }

template <int N>
DEVFN void cpwait() { asm volatile("cp.async.wait_group %0;" ::"n"(N) : "memory"); }

#define LDSM4(r, addr)                                                       \
    asm volatile("ldmatrix.sync.aligned.m8n8.x4.shared.b16 {%0,%1,%2,%3}, [%4];" \
                 : "=r"((r)[0]), "=r"((r)[1]), "=r"((r)[2]), "=r"((r)[3])    \
                 : "r"(addr))

#define MMA16816(acc, a, b0v, b1v)                                           \
    asm volatile("mma.sync.aligned.m16n8k16.row.col.f32.bf16.bf16.f32 "     \
                 "{%0,%1,%2,%3}, {%4,%5,%6,%7}, {%8,%9}, {%0,%1,%2,%3};"    \
                 : "+f"((acc)[0]), "+f"((acc)[1]), "+f"((acc)[2]), "+f"((acc)[3]) \
                 : "r"((a)[0]), "r"((a)[1]), "r"((a)[2]), "r"((a)[3]),       \
                   "r"(b0v), "r"(b1v))

#define SWZ(o) ((unsigned)(o) ^ ((((unsigned)(o)) >> 3) & 0x70u))

DEVFN void split_store_pair(__nv_bfloat16* H, __nv_bfloat16* L, size_t off,
                            float v0, float v1) {
    __nv_bfloat16 h0 = __float2bfloat16(v0), h1 = __float2bfloat16(v1);
    __nv_bfloat16 l0 = __float2bfloat16(v0 - __bfloat162float(h0));
    __nv_bfloat16 l1 = __float2bfloat16(v1 - __bfloat162float(h1));
    __nv_bfloat162 hp; hp.x = h0; hp.y = h1;
    __nv_bfloat162 lp; lp.x = l0; lp.y = l1;
    *(__nv_bfloat162*)(H + off) = hp;
    *(__nv_bfloat162*)(L + off) = lp;
}

// ---------------- weight prep: transpose [K,N] fp32 -> [N,K] bf16 hi/lo ----------------
__global__ void prep_w(const float* __restrict__ W, __nv_bfloat16* __restrict__ Th,
                       __nv_bfloat16* __restrict__ Tl) {
    __shared__ float t[32][33];
    int bx = blockIdx.x * 32, by = blockIdx.y * 32;
#pragma unroll
    for (int i = threadIdx.y; i < 32; i += 8)
        t[i][threadIdx.x] = W[(size_t)(by + i) * 1024 + bx + threadIdx.x];
    __syncthreads();
#pragma unroll
    for (int i = threadIdx.y; i < 32; i += 8) {
        float v = t[threadIdx.x][i];  // = W[by+tx][bx+i]
        __nv_bfloat16 h = __float2bfloat16(v);
        __nv_bfloat16 l = __float2bfloat16(v - __bfloat162float(h));
        size_t o = (size_t)(bx + i) * 1024 + by + threadIdx.x;  // Th[n][k]
        Th[o] = h;
        Tl[o] = l;
    }
}

// ---------------- input split: fp32 -> bf16 hi/lo ----------------
__global__ void __launch_bounds__(256) split_x(const float* __restrict__ x,
                                               __nv_bfloat16* __restrict__ xh,
                                               __nv_bfloat16* __restrict__ xl) {
    size_t i = ((size_t)blockIdx.x * 256 + threadIdx.x) * 4;
    float4 v = *(const float4*)(x + i);
    split_store_pair(xh, xl, i + 0, v.x, v.y);
    split_store_pair(xh, xl, i + 2, v.z, v.w);
}

// ---------------- loader: one chunk into one stage via cp.async ----------------
DEVFN void load_chunk(unsigned stage, const __nv_bfloat16* __restrict__ Ah,
                      const __nv_bfloat16* __restrict__ Al,
                      const __nv_bfloat16* __restrict__ Bh,
                      const __nv_bfloat16* __restrict__ Bl, int tm, int tn, int c,
                      int tid) {
    // A: 128 rows x 64 bf16 = 1024 x 16B granules (hi + lo)
    const size_t acol = (size_t)c * 64;
#pragma unroll
    for (int i = 0; i < 4; i++) {
        int g = i * 256 + tid;
        int row = g >> 3, k16 = g & 7;
        size_t so = (size_t)(tm * 128 + row) * 1024 + acol + k16 * 8;
        unsigned dst = stage + SWZ(row * 128 + k16 * 16);
        CP16(dst, Ah + so);
        CP16(dst + 16384, Al + so);
    }
    // B: 128 n-rows x 64 bf16 (hi + lo)
#pragma unroll
    for (int i = 0; i < 4; i++) {
        int g = i * 256 + tid;
        int row = g >> 3, k16 = g & 7;
        size_t so = (size_t)(tn * 128 + row) * 1024 + acol + k16 * 8;
        unsigned dst = stage + 32768 + SWZ(row * 128 + k16 * 16);
        CP16(dst, Bh + so);
        CP16(dst + 16384, Bl + so);
    }
}

// ---------------- bf16x3-split HMMA GEMM: C = A @ W^T + bias ----------------
// mode 0: write fp32 C. mode 1: ReLU then write split bf16 hi/lo (Ch, Cl).
__global__ void __launch_bounds__(256, 1)
gemm_k(const __nv_bfloat16* __restrict__ Ah, const __nv_bfloat16* __restrict__ Al,
       const __nv_bfloat16* __restrict__ Bh, const __nv_bfloat16* __restrict__ Bl,
       const float* __restrict__ bias, float* __restrict__ Cf,
       __nv_bfloat16* __restrict__ Ch, __nv_bfloat16* __restrict__ Cl, int mode) {
    extern __shared__ char sm[];
    unsigned sb = smem_u32(sm);
    int tid = threadIdx.x;
    int tn = blockIdx.x, tm = blockIdx.y;
    int lane = tid & 31, wid = tid >> 5;
    int wm = wid >> 2, wn = wid & 3;  // warp grid 2(M) x 4(N), warp tile 64x32

    // ldmatrix per-lane address components
    int a_dr = lane & 15;               // A row within m16 tile
    int a_kb = (lane >> 4) << 4;        // 0 / 16B half
    int b_dr = (lane & 7) | ((lane >> 4) << 3);
    int b_kb = ((lane >> 3) & 1) << 4;

    unsigned aOff[4], aMsk[4], bOff[2], bMsk[2];
#pragma unroll
    for (int mt = 0; mt < 4; mt++) {
        int row = wm * 64 + mt * 16 + a_dr;
        aOff[mt] = (unsigned)row << 7;
        aMsk[mt] = (unsigned)(row & 7) << 4;
    }
#pragma unroll
    for (int np = 0; np < 2; np++) {
        int row = wn * 32 + np * 16 + b_dr;
        bOff[np] = (unsigned)row << 7;
        bMsk[np] = (unsigned)(row & 7) << 4;
    }

    float acc[4][4][4];
#pragma unroll
    for (int mt = 0; mt < 4; mt++)
#pragma unroll
        for (int nt = 0; nt < 4; nt++)
#pragma unroll
            for (int i = 0; i < 4; i++) acc[mt][nt][i] = 0.f;

    load_chunk(sb, Ah, Al, Bh, Bl, tm, tn, 0, tid);
    cpcommit();

    for (int c = 0; c < NCHUNK; c++) {
        unsigned stage = sb + (unsigned)(c & 1) * STAGE;
        if (c + 1 < NCHUNK) {
            load_chunk(sb + (unsigned)((c + 1) & 1) * STAGE, Ah, Al, Bh, Bl, tm, tn,
                       c + 1, tid);
            cpcommit();
            cpwait<1>();  // group(c) complete, group(c+1) may remain in flight
        } else {
            cpwait<0>();
        }
        __syncthreads();

#pragma unroll
        for (int kk = 0; kk < 4; kk++) {
            unsigned ah[4][4], al[4][4], bh[4][2], bl[4][2];
            unsigned colA = kk * 32 + a_kb;
            unsigned colB = kk * 32 + b_kb;
#pragma unroll
            for (int mt = 0; mt < 4; mt++) {
                unsigned ad = stage + aOff[mt] + (colA ^ aMsk[mt]);
                LDSM4(ah[mt], ad);
                LDSM4(al[mt], ad + 16384);
            }
#pragma unroll
            for (int np = 0; np < 2; np++) {
                unsigned bd = stage + 32768 + bOff[np] + (colB ^ bMsk[np]);
                unsigned r[4];
                LDSM4(r, bd);
                bh[np * 2][0] = r[0]; bh[np * 2][1] = r[1];
                bh[np * 2 + 1][0] = r[2]; bh[np * 2 + 1][1] = r[3];
                LDSM4(r, bd + 16384);
                bl[np * 2][0] = r[0]; bl[np * 2][1] = r[1];
                bl[np * 2 + 1][0] = r[2]; bl[np * 2 + 1][1] = r[3];
            }
#pragma unroll
            for (int mt = 0; mt < 4; mt++)
#pragma unroll
                for (int nt = 0; nt < 4; nt++) {
                    MMA16816(acc[mt][nt], ah[mt], bh[nt][0], bh[nt][1]);
                    MMA16816(acc[mt][nt], ah[mt], bl[nt][0], bl[nt][1]);
                    MMA16816(acc[mt][nt], al[mt], bh[nt][0], bh[nt][1]);
                }
        }
        __syncthreads();  // all warps done with stage(c) before it is overwritten
    }

    // ---- epilogue ----
#pragma unroll
    for (int mt = 0; mt < 4; mt++) {
        int r0 = tm * 128 + wm * 64 + mt * 16 + (lane >> 2);
#pragma unroll
        for (int nt = 0; nt < 4; nt++) {
            int n = tn * 128 + wn * 32 + nt * 8 + (lane & 3) * 2;
            float b0 = bias[n], b1 = bias[n + 1];
            float v00 = acc[mt][nt][0] + b0, v01 = acc[mt][nt][1] + b1;
            float v10 = acc[mt][nt][2] + b0, v11 = acc[mt][nt][3] + b1;
            if (mode == 0) {
                *(float2*)(Cf + (size_t)r0 * Nc + n) = make_float2(v00, v01);
                *(float2*)(Cf + (size_t)(r0 + 8) * Nc + n) = make_float2(v10, v11);
            } else {
                v00 = fmaxf(v00, 0.f); v01 = fmaxf(v01, 0.f);
                v10 = fmaxf(v10, 0.f); v11 = fmaxf(v11, 0.f);
                split_store_pair(Ch, Cl, (size_t)r0 * Nc + n, v00, v01);
                split_store_pair(Ch, Cl, (size_t)(r0 + 8) * Nc + n, v10, v11);
            }
        }
    }
}

// ---------------- per-token 8x8 attention (one block per token) ----------------
__global__ void __launch_bounds__(128) attn_k(const float* __restrict__ q,
                                              const float* __restrict__ k,
                                              const float* __restrict__ v,
                                              __nv_bfloat16* __restrict__ aoh,
                                              __nv_bfloat16* __restrict__ aol,
                                              float* __restrict__ aw) {
    constexpr int PS = 136;  // padded row stride
    __shared__ float sQ[8 * PS], sK[8 * PS], sV[8 * PS], sS[64];
    int tok = blockIdx.x, t = threadIdx.x;
    const float* qp = q + (size_t)tok * 1024;
    const float* kp = k + (size_t)tok * 1024;
    const float* vp = v + (size_t)tok * 1024;
#pragma unroll
    for (int i = 0; i < 2; i++) {
        int e = (i * 128 + t) * 4;
        int h = e >> 7, d = e & 127;
        *(float4*)&sQ[h * PS + d] = *(const float4*)(qp + e);
        *(float4*)&sK[h * PS + d] = *(const float4*)(kp + e);
        *(float4*)&sV[h * PS + d] = *(const float4*)(vp + e);
    }
    __syncthreads();
    if (t < 64) {
        int h = t >> 3, tt = t & 7;
        float s = 0.f;
#pragma unroll 16
        for (int i = 0; i < 128; i++) s += sQ[h * PS + i] * sK[tt * PS + i];
        sS[t] = s * 0.08838834764831845f;  // 1/sqrt(128)
    }
    __syncthreads();
    if (t < 8) {
        float m = -1e30f;
#pragma unroll
        for (int j = 0; j < 8; j++) m = fmaxf(m, sS[t * 8 + j]);
        float e[8], sum = 0.f;
#pragma unroll
        for (int j = 0; j < 8; j++) { e[j] = expf(sS[t * 8 + j] - m); sum += e[j]; }
        float inv = 1.f / sum;
#pragma unroll
        for (int j = 0; j < 8; j++) {
            float w = e[j] * inv;
            sS[t * 8 + j] = w;
            aw[(size_t)tok * 64 + t * 8 + j] = w;
        }
    }
    __syncthreads();
    int h = t >> 4, d0 = (t & 15) * 8;
    float o[8];
#pragma unroll
    for (int j = 0; j < 8; j++) o[j] = 0.f;
#pragma unroll
    for (int tt = 0; tt < 8; tt++) {
        float w = sS[h * 8 + tt];
#pragma unroll
        for (int j = 0; j < 8; j++) o[j] += w * sV[tt * PS + d0 + j];
    }
    size_t base = (size_t)tok * 1024 + h * 128 + d0;
#pragma unroll
    for (int j = 0; j < 4; j++)
        split_store_pair(aoh, aol, base + 2 * j, o[2 * j], o[2 * j + 1]);
}

// ---------------- launch ----------------
extern "C" void kernel_launch(void* const* d_in, const int* in_sizes, int n_in,
                              void* d_out, int out_size) {
    (void)in_sizes; (void)n_in;
    const float* x  = (const float*)d_in[0];
    const float* Wq = (const float*)d_in[1];
    const float* bq = (const float*)d_in[2];
    const float* Wk = (const float*)d_in[3];
    const float* bk = (const float*)d_in[4];
    const float* Wv = (const float*)d_in[5];
    const float* bv = (const float*)d_in[6];
    const float* W1 = (const float*)d_in[7];
    const float* b1 = (const float*)d_in[8];
    const float* W2 = (const float*)d_in[9];
    const float* b2 = (const float*)d_in[10];

    float *q, *k, *v, *awf;
    __nv_bfloat16 *xh, *xl, *aoh, *aol, *hh, *hl, *wh, *wl;
    cudaGetSymbolAddress((void**)&q, g_q);
    cudaGetSymbolAddress((void**)&k, g_k);
    cudaGetSymbolAddress((void**)&v, g_v);
    cudaGetSymbolAddress((void**)&xh, g_xh);
    cudaGetSymbolAddress((void**)&xl, g_xl);
    cudaGetSymbolAddress((void**)&aoh, g_aoh);
    cudaGetSymbolAddress((void**)&aol, g_aol);
    cudaGetSymbolAddress((void**)&hh, g_hh);
    cudaGetSymbolAddress((void**)&hl, g_hl);
    cudaGetSymbolAddress((void**)&wh, g_wh);
    cudaGetSymbolAddress((void**)&wl, g_wl);
    cudaGetSymbolAddress((void**)&awf, g_awf);

    cudaFuncSetAttribute(gemm_k, cudaFuncAttributeMaxDynamicSharedMemorySize,
                         SMEM_BYTES);

    // input split + weight prep (slots: 0=Wq 1=Wk 2=Wv 3=W1 4=W2)
    split_x<<<MTOT * Dc / 1024, 256>>>(x, xh, xl);
    {
        dim3 pg(32, 32), pb(32, 8);
        const float* Ws[5] = {Wq, Wk, Wv, W1, W2};
        for (int i = 0; i < 5; i++)
            prep_w<<<pg, pb>>>(Ws[i], wh + (size_t)i * 1048576, wl + (size_t)i * 1048576);
    }

    const long long FF = (long long)MTOT * Dc;     // 16777216
    const long long AW = (long long)MTOT * 64;     // 1048576
    float* out_ff = (float*)d_out;
    float* aw = ((long long)out_size >= FF + AW) ? (out_ff + FF) : awf;

    dim3 gg(Nc / 128, MTOT / 128);  // (8, 128)
    gemm_k<<<gg, 256, SMEM_BYTES>>>(xh, xl, wh + 0 * 1048576, wl + 0 * 1048576, bq,
                                    q, nullptr, nullptr, 0);
    gemm_k<<<gg, 256, SMEM_BYTES>>>(xh, xl, wh + 1 * 1048576, wl + 1 * 1048576, bk,
                                    k, nullptr, nullptr, 0);
    gemm_k<<<gg, 256, SMEM_BYTES>>>(xh, xl, wh + 2 * 1048576, wl + 2 * 1048576, bv,
                                    v, nullptr, nullptr, 0);
    attn_k<<<MTOT, 128>>>(q, k, v, aoh, aol, aw);
    gemm_k<<<gg, 256, SMEM_BYTES>>>(aoh, aol, wh + 3 * 1048576, wl + 3 * 1048576,
                                    b1, nullptr, hh, hl, 1);
    gemm_k<<<gg, 256, SMEM_BYTES>>>(hh, hl, wh + 4 * 1048576, wl + 4 * 1048576, b2,
                                    out_ff, nullptr, nullptr, 0);
}

// round 14
// speedup vs baseline: 1.3203x; 1.3203x over previous
#include <cuda_runtime.h>
#include <cuda_fp16.h>
#include <cstdint>

// ---------------- problem constants ----------------
constexpr int Bc = 4, Sc = 4096, Dc = 1024;
constexpr int MTOT = Bc * Sc;   // 16384 rows
constexpr int Kc = 1024, Nc = 1024;
constexpr int NCHUNK = 16;      // K chunks of 64
constexpr int NSTAGE = 3;
constexpr int STAGE = 49152;    // {Ah 16K, Al 16K, B 16K}
constexpr int SMEM_BYTES = NSTAGE * STAGE;  // 144 KB

// ---------------- device scratch (no allocations allowed) ----------------
__device__ float g_q[(size_t)MTOT * Dc];
__device__ float g_k[(size_t)MTOT * Dc];
__device__ float g_v[(size_t)MTOT * Dc];
__device__ __half g_xh[(size_t)MTOT * Dc];   // split input x (fp16 hi)
__device__ __half g_xl[(size_t)MTOT * Dc];   // fp16 lo
__device__ __half g_aoh[(size_t)MTOT * Dc];  // split attn output
__device__ __half g_aol[(size_t)MTOT * Dc];
__device__ __half g_hh[(size_t)MTOT * Dc];   // split hidden (post-ReLU)
__device__ __half g_hl[(size_t)MTOT * Dc];
__device__ __half g_wt[5u * 1024 * 1024];    // transposed weights, fp16 (unsplit)
__device__ float g_awf[(size_t)MTOT * 64];   // attn_weights fallback sink

// ---------------- portable PTX helpers (NO 'a'-gated instructions) ----------------
#define DEVFN __device__ __forceinline__

DEVFN unsigned smem_u32(const void* p) {
    unsigned a;
    asm("{ .reg .u64 t; cvta.to.shared.u64 t, %1; cvt.u32.u64 %0, t; }" : "=r"(a) : "l"(p));
    return a;
}

#define CP16(dst, src)                                                       \
    asm volatile("cp.async.cg.shared.global [%0], [%1], 16;" ::"r"(dst),     \
                 "l"(src) : "memory")

DEVFN void cpcommit() { asm volatile("cp.async.commit_group;" ::: "memory"); }

template <int N>
DEVFN void cpwait() { asm volatile("cp.async.wait_group %0;" ::"n"(N) : "memory"); }

#define LDSM4(r, addr)                                                       \
    asm volatile("ldmatrix.sync.aligned.m8n8.x4.shared.b16 {%0,%1,%2,%3}, [%4];" \
                 : "=r"((r)[0]), "=r"((r)[1]), "=r"((r)[2]), "=r"((r)[3])    \
                 : "r"(addr))

#define MMA16816(acc, a, b0v, b1v)                                           \
    asm volatile("mma.sync.aligned.m16n8k16.row.col.f32.f16.f16.f32 "       \
                 "{%0,%1,%2,%3}, {%4,%5,%6,%7}, {%8,%9}, {%0,%1,%2,%3};"    \
                 : "+f"((acc)[0]), "+f"((acc)[1]), "+f"((acc)[2]), "+f"((acc)[3]) \
                 : "r"((a)[0]), "r"((a)[1]), "r"((a)[2]), "r"((a)[3]),       \
                   "r"(b0v), "r"(b1v))

#define SWZ(o) ((unsigned)(o) ^ ((((unsigned)(o)) >> 3) & 0x70u))

DEVFN void split_store_pair(__half* H, __half* L, size_t off, float v0, float v1) {
    __half h0 = __float2half_rn(v0), h1 = __float2half_rn(v1);
    __half l0 = __float2half_rn(v0 - __half2float(h0));
    __half l1 = __float2half_rn(v1 - __half2float(h1));
    __half2 hp; hp.x = h0; hp.y = h1;
    __half2 lp; lp.x = l0; lp.y = l1;
    *(__half2*)(H + off) = hp;
    *(__half2*)(L + off) = lp;
}

// ---------------- weight prep (fused): transpose [K,N] fp32 -> [N,K] fp16 ----------------
__global__ void prep_all(const float* __restrict__ W0, const float* __restrict__ W1,
                         const float* __restrict__ W2, const float* __restrict__ W3,
                         const float* __restrict__ W4, __half* __restrict__ T) {
    __shared__ float t[32][33];
    const float* Ws[5] = {W0, W1, W2, W3, W4};
    const float* W = Ws[blockIdx.z];
    __half* Th = T + (size_t)blockIdx.z * 1048576;
    int bx = blockIdx.x * 32, by = blockIdx.y * 32;
#pragma unroll
    for (int i = threadIdx.y; i < 32; i += 8)
        t[i][threadIdx.x] = W[(size_t)(by + i) * 1024 + bx + threadIdx.x];
    __syncthreads();
#pragma unroll
    for (int i = threadIdx.y; i < 32; i += 8) {
        float v = t[threadIdx.x][i];  // = W[by+tx][bx+i]
        Th[(size_t)(bx + i) * 1024 + by + threadIdx.x] = __float2half_rn(v);
    }
}

// ---------------- input split: fp32 -> fp16 hi/lo ----------------
__global__ void __launch_bounds__(256) split_x(const float* __restrict__ x,
                                               __half* __restrict__ xh,
                                               __half* __restrict__ xl) {
    size_t i = ((size_t)blockIdx.x * 256 + threadIdx.x) * 4;
    float4 v = *(const float4*)(x + i);
    split_store_pair(xh, xl, i + 0, v.x, v.y);
    split_store_pair(xh, xl, i + 2, v.z, v.w);
}

// ---------------- loader: one chunk into one stage via cp.async ----------------
DEVFN void load_chunk(unsigned stage, const __half* __restrict__ Ah,
                      const __half* __restrict__ Al, const __half* __restrict__ Bt,
                      int tm, int tn, int c, int tid) {
    const size_t acol = (size_t)c * 64;
#pragma unroll
    for (int i = 0; i < 4; i++) {
        int g = i * 256 + tid;
        int row = g >> 3, k16 = g & 7;
        unsigned dsw = SWZ(row * 128 + k16 * 16);
        size_t soA = (size_t)(tm * 128 + row) * 1024 + acol + k16 * 8;
        CP16(stage + dsw, Ah + soA);
        CP16(stage + 16384 + dsw, Al + soA);
        size_t soB = (size_t)(tn * 128 + row) * 1024 + acol + k16 * 8;
        CP16(stage + 32768 + dsw, Bt + soB);
    }
}

// ---------------- fp16 2-MMA split GEMM: C = (Ah+Al) @ W^T + bias ----------------
// mode 0: write fp32 C. mode 1: ReLU then write split fp16 hi/lo (Ch, Cl).
__global__ void __launch_bounds__(256, 1)
gemm_k(const __half* __restrict__ Ah, const __half* __restrict__ Al,
       const __half* __restrict__ Bt, const float* __restrict__ bias,
       float* __restrict__ Cf, __half* __restrict__ Ch, __half* __restrict__ Cl,
       int mode) {
    extern __shared__ char sm[];
    unsigned sb = smem_u32(sm);
    int tid = threadIdx.x;
    int tn = blockIdx.x, tm = blockIdx.y;
    int lane = tid & 31, wid = tid >> 5;
    int wm = wid & 3, wn = wid >> 2;  // warp grid 4(M) x 2(N), warp tile 32x64

    // ldmatrix per-lane address components
    int a_dr = lane & 15;             // A row within m16 tile
    int a_kb = (lane >> 4) << 4;      // 16B half of k16 block
    int b_dr = (lane & 7) | ((lane >> 4) << 3);
    int b_kb = ((lane >> 3) & 1) << 4;

    unsigned aOff[2], aMsk[2], bOff[4], bMsk[4];
#pragma unroll
    for (int mt = 0; mt < 2; mt++) {
        int row = wm * 32 + mt * 16 + a_dr;
        aOff[mt] = (unsigned)row << 7;
        aMsk[mt] = (unsigned)(row & 7) << 4;
    }
#pragma unroll
    for (int np = 0; np < 4; np++) {
        int row = wn * 64 + np * 16 + b_dr;
        bOff[np] = (unsigned)row << 7;
        bMsk[np] = (unsigned)(row & 7) << 4;
    }

    float acc[2][8][4];
#pragma unroll
    for (int mt = 0; mt < 2; mt++)
#pragma unroll
        for (int nt = 0; nt < 8; nt++)
#pragma unroll
            for (int i = 0; i < 4; i++) acc[mt][nt][i] = 0.f;

    load_chunk(sb + 0 * STAGE, Ah, Al, Bt, tm, tn, 0, tid);
    cpcommit();
    load_chunk(sb + 1 * STAGE, Ah, Al, Bt, tm, tn, 1, tid);
    cpcommit();

    int sidx = 0;  // stage index of chunk c
    for (int c = 0; c < NCHUNK; c++) {
        if (c + 2 < NCHUNK) cpwait<1>(); else cpwait<0>();
        __syncthreads();
        if (c + 2 < NCHUNK) {
            int ns = sidx + 2; if (ns >= NSTAGE) ns -= NSTAGE;
            load_chunk(sb + (unsigned)ns * STAGE, Ah, Al, Bt, tm, tn, c + 2, tid);
            cpcommit();
        }
        unsigned stage = sb + (unsigned)sidx * STAGE;

#pragma unroll
        for (int kk = 0; kk < 4; kk++) {
            unsigned ah[2][4], al[2][4], b[8][2];
            unsigned colA = kk * 32 + a_kb;
            unsigned colB = kk * 32 + b_kb;
#pragma unroll
            for (int mt = 0; mt < 2; mt++) {
                unsigned ad = stage + aOff[mt] + (colA ^ aMsk[mt]);
                LDSM4(ah[mt], ad);
                LDSM4(al[mt], ad + 16384);
            }
#pragma unroll
            for (int np = 0; np < 4; np++) {
                unsigned bd = stage + 32768 + bOff[np] + (colB ^ bMsk[np]);
                unsigned r[4];
                LDSM4(r, bd);
                b[np * 2][0] = r[0]; b[np * 2][1] = r[1];
                b[np * 2 + 1][0] = r[2]; b[np * 2 + 1][1] = r[3];
            }
#pragma unroll
            for (int mt = 0; mt < 2; mt++)
#pragma unroll
                for (int nt = 0; nt < 8; nt++) {
                    MMA16816(acc[mt][nt], ah[mt], b[nt][0], b[nt][1]);
                    MMA16816(acc[mt][nt], al[mt], b[nt][0], b[nt][1]);
                }
        }
        if (++sidx >= NSTAGE) sidx = 0;
    }

    // ---- epilogue ----
#pragma unroll
    for (int nt = 0; nt < 8; nt++) {
        int n = tn * 128 + wn * 64 + nt * 8 + (lane & 3) * 2;
        float b0 = bias[n], b1 = bias[n + 1];
#pragma unroll
        for (int mt = 0; mt < 2; mt++) {
            int r0 = tm * 128 + wm * 32 + mt * 16 + (lane >> 2);
            float v00 = acc[mt][nt][0] + b0, v01 = acc[mt][nt][1] + b1;
            float v10 = acc[mt][nt][2] + b0, v11 = acc[mt][nt][3] + b1;
            if (mode == 0) {
                *(float2*)(Cf + (size_t)r0 * Nc + n) = make_float2(v00, v01);
                *(float2*)(Cf + (size_t)(r0 + 8) * Nc + n) = make_float2(v10, v11);
            } else {
                v00 = fmaxf(v00, 0.f); v01 = fmaxf(v01, 0.f);
                v10 = fmaxf(v10, 0.f); v11 = fmaxf(v11, 0.f);
                split_store_pair(Ch, Cl, (size_t)r0 * Nc + n, v00, v01);
                split_store_pair(Ch, Cl, (size_t)(r0 + 8) * Nc + n, v10, v11);
            }
        }
    }
}

// ---------------- per-token 8x8 attention (one block per token) ----------------
__global__ void __launch_bounds__(128) attn_k(const float* __restrict__ q,
                                              const float* __restrict__ k,
                                              const float* __restrict__ v,
                                              __half* __restrict__ aoh,
                                              __half* __restrict__ aol,
                                              float* __restrict__ aw) {
    constexpr int PS = 136;  // padded row stride
    __shared__ float sQ[8 * PS], sK[8 * PS], sV[8 * PS], sS[64];
    int tok = blockIdx.x, t = threadIdx.x;
    const float* qp = q + (size_t)tok * 1024;
    const float* kp = k + (size_t)tok * 1024;
    const float* vp = v + (size_t)tok * 1024;
#pragma unroll
    for (int i = 0; i < 2; i++) {
        int e = (i * 128 + t) * 4;
        int h = e >> 7, d = e & 127;
        *(float4*)&sQ[h * PS + d] = *(const float4*)(qp + e);
        *(float4*)&sK[h * PS + d] = *(const float4*)(kp + e);
        *(float4*)&sV[h * PS + d] = *(const float4*)(vp + e);
    }
    __syncthreads();
    if (t < 64) {
        int h = t >> 3, tt = t & 7;
        float s = 0.f;
#pragma unroll 16
        for (int i = 0; i < 128; i++) s += sQ[h * PS + i] * sK[tt * PS + i];
        sS[t] = s * 0.08838834764831845f;  // 1/sqrt(128)
    }
    __syncthreads();
    if (t < 8) {
        float m = -1e30f;
#pragma unroll
        for (int j = 0; j < 8; j++) m = fmaxf(m, sS[t * 8 + j]);
        float e[8], sum = 0.f;
#pragma unroll
        for (int j = 0; j < 8; j++) { e[j] = expf(sS[t * 8 + j] - m); sum += e[j]; }
        float inv = 1.f / sum;
#pragma unroll
        for (int j = 0; j < 8; j++) {
            float w = e[j] * inv;
            sS[t * 8 + j] = w;
            aw[(size_t)tok * 64 + t * 8 + j] = w;
        }
    }
    __syncthreads();
    int h = t >> 4, d0 = (t & 15) * 8;
    float o[8];
#pragma unroll
    for (int j = 0; j < 8; j++) o[j] = 0.f;
#pragma unroll
    for (int tt = 0; tt < 8; tt++) {
        float w = sS[h * 8 + tt];
#pragma unroll
        for (int j = 0; j < 8; j++) o[j] += w * sV[tt * PS + d0 + j];
    }
    size_t base = (size_t)tok * 1024 + h * 128 + d0;
#pragma unroll
    for (int j = 0; j < 4; j++)
        split_store_pair(aoh, aol, base + 2 * j, o[2 * j], o[2 * j + 1]);
}

// ---------------- launch ----------------
extern "C" void kernel_launch(void* const* d_in, const int* in_sizes, int n_in,
                              void* d_out, int out_size) {
    (void)in_sizes; (void)n_in;
    const float* x  = (const float*)d_in[0];
    const float* Wq = (const float*)d_in[1];
    const float* bq = (const float*)d_in[2];
    const float* Wk = (const float*)d_in[3];
    const float* bk = (const float*)d_in[4];
    const float* Wv = (const float*)d_in[5];
    const float* bv = (const float*)d_in[6];
    const float* W1 = (const float*)d_in[7];
    const float* b1 = (const float*)d_in[8];
    const float* W2 = (const float*)d_in[9];
    const float* b2 = (const float*)d_in[10];

    float *q, *k, *v, *awf;
    __half *xh, *xl, *aoh, *aol, *hh, *hl, *wt;
    cudaGetSymbolAddress((void**)&q, g_q);
    cudaGetSymbolAddress((void**)&k, g_k);
    cudaGetSymbolAddress((void**)&v, g_v);
    cudaGetSymbolAddress((void**)&xh, g_xh);
    cudaGetSymbolAddress((void**)&xl, g_xl);
    cudaGetSymbolAddress((void**)&aoh, g_aoh);
    cudaGetSymbolAddress((void**)&aol, g_aol);
    cudaGetSymbolAddress((void**)&hh, g_hh);
    cudaGetSymbolAddress((void**)&hl, g_hl);
    cudaGetSymbolAddress((void**)&wt, g_wt);
    cudaGetSymbolAddress((void**)&awf, g_awf);

    cudaFuncSetAttribute(gemm_k, cudaFuncAttributeMaxDynamicSharedMemorySize,
                         SMEM_BYTES);

    // launches #1,#2: input split (two halves so launch #6 = gemm_k for ncu -s 5)
    split_x<<<8192, 256>>>(x, xh, xl);
    split_x<<<8192, 256>>>(x + 8388608, xh + 8388608, xl + 8388608);
    // launch #3: fused weight prep (slots: 0=Wq 1=Wk 2=Wv 3=W1 4=W2)
    prep_all<<<dim3(32, 32, 5), dim3(32, 8)>>>(Wq, Wk, Wv, W1, W2, wt);

    const long long FF = (long long)MTOT * Dc;  // 16777216
    const long long AW = (long long)MTOT * 64;  // 1048576
    float* out_ff = (float*)d_out;
    float* aw = ((long long)out_size >= FF + AW) ? (out_ff + FF) : awf;

    dim3 gg(Nc / 128, MTOT / 128);  // (8, 128)
    gemm_k<<<gg, 256, SMEM_BYTES>>>(xh, xl, wt + 0u * 1048576, bq, q, nullptr,
                                    nullptr, 0);                       // #4
    gemm_k<<<gg, 256, SMEM_BYTES>>>(xh, xl, wt + 1u * 1048576, bk, k, nullptr,
                                    nullptr, 0);                       // #5
    gemm_k<<<gg, 256, SMEM_BYTES>>>(xh, xl, wt + 2u * 1048576, bv, v, nullptr,
                                    nullptr, 0);                       // #6 (profiled)
    attn_k<<<MTOT, 128>>>(q, k, v, aoh, aol, aw);                      // #7
    gemm_k<<<gg, 256, SMEM_BYTES>>>(aoh, aol, wt + 3u * 1048576, b1, nullptr, hh,
                                    hl, 1);                            // #8
    gemm_k<<<gg, 256, SMEM_BYTES>>>(hh, hl, wt + 4u * 1048576, b2, out_ff, nullptr,
                                    nullptr, 0);                       // #9
}

// round 15
// speedup vs baseline: 1.3205x; 1.0001x over previous
#include <cuda_runtime.h>
#include <cuda_fp16.h>
#include <cstdint>

// ---------------- problem constants ----------------
constexpr int Bc = 4, Sc = 4096, Dc = 1024;
constexpr int MTOT = Bc * Sc;   // 16384 rows
constexpr int Kc = 1024, Nc = 1024;
constexpr int NCHUNK = 16;      // K chunks of 64
constexpr int NSTAGE = 3;
constexpr int STAGE = 49152;    // {Ah 16K, Al 16K, B 16K}
constexpr int SMEM_BYTES = NSTAGE * STAGE;  // 144 KB

// ---------------- device scratch (no allocations allowed) ----------------
__device__ float g_q[(size_t)MTOT * Dc];
__device__ float g_k[(size_t)MTOT * Dc];
__device__ float g_v[(size_t)MTOT * Dc];
__device__ __half g_xh[(size_t)MTOT * Dc];   // split input x (fp16 hi)
__device__ __half g_xl[(size_t)MTOT * Dc];   // fp16 lo
__device__ __half g_aoh[(size_t)MTOT * Dc];  // split attn output
__device__ __half g_aol[(size_t)MTOT * Dc];
__device__ __half g_hh[(size_t)MTOT * Dc];   // split hidden (post-ReLU)
__device__ __half g_hl[(size_t)MTOT * Dc];
__device__ __half g_wt[5u * 1024 * 1024];    // transposed weights, fp16 (unsplit)
__device__ float g_awf[(size_t)MTOT * 64];   // attn_weights fallback sink

// ---------------- portable PTX helpers (NO 'a'-gated instructions) ----------------
#define DEVFN __device__ __forceinline__

DEVFN unsigned smem_u32(const void* p) {
    unsigned a;
    asm("{ .reg .u64 t; cvta.to.shared.u64 t, %1; cvt.u32.u64 %0, t; }" : "=r"(a) : "l"(p));
    return a;
}

#define CP16(dst, src)                                                       \
    asm volatile("cp.async.cg.shared.global [%0], [%1], 16;" ::"r"(dst),     \
                 "l"(src) : "memory")

DEVFN void cpcommit() { asm volatile("cp.async.commit_group;" ::: "memory"); }

template <int N>
DEVFN void cpwait() { asm volatile("cp.async.wait_group %0;" ::"n"(N) : "memory"); }

#define LDSM4(r, addr)                                                       \
    asm volatile("ldmatrix.sync.aligned.m8n8.x4.shared.b16 {%0,%1,%2,%3}, [%4];" \
                 : "=r"((r)[0]), "=r"((r)[1]), "=r"((r)[2]), "=r"((r)[3])    \
                 : "r"(addr))

#define MMA16816(acc, a, b0v, b1v)                                           \
    asm volatile("mma.sync.aligned.m16n8k16.row.col.f32.f16.f16.f32 "       \
                 "{%0,%1,%2,%3}, {%4,%5,%6,%7}, {%8,%9}, {%0,%1,%2,%3};"    \
                 : "+f"((acc)[0]), "+f"((acc)[1]), "+f"((acc)[2]), "+f"((acc)[3]) \
                 : "r"((a)[0]), "r"((a)[1]), "r"((a)[2]), "r"((a)[3]),       \
                   "r"(b0v), "r"(b1v))

#define SWZ(o) ((unsigned)(o) ^ ((((unsigned)(o)) >> 3) & 0x70u))

DEVFN void split_store_pair(__half* H, __half* L, size_t off, float v0, float v1) {
    __half h0 = __float2half_rn(v0), h1 = __float2half_rn(v1);
    __half l0 = __float2half_rn(v0 - __half2float(h0));
    __half l1 = __float2half_rn(v1 - __half2float(h1));
    __half2 hp; hp.x = h0; hp.y = h1;
    __half2 lp; lp.x = l0; lp.y = l1;
    *(__half2*)(H + off) = hp;
    *(__half2*)(L + off) = lp;
}

// ---------------- weight prep (fused): transpose [K,N] fp32 -> [N,K] fp16 ----------------
__global__ void prep_all(const float* __restrict__ W0, const float* __restrict__ W1,
                         const float* __restrict__ W2, const float* __restrict__ W3,
                         const float* __restrict__ W4, __half* __restrict__ T) {
    __shared__ float t[32][33];
    const float* Ws[5] = {W0, W1, W2, W3, W4};
    const float* W = Ws[blockIdx.z];
    __half* Th = T + (size_t)blockIdx.z * 1048576;
    int bx = blockIdx.x * 32, by = blockIdx.y * 32;
#pragma unroll
    for (int i = threadIdx.y; i < 32; i += 8)
        t[i][threadIdx.x] = W[(size_t)(by + i) * 1024 + bx + threadIdx.x];
    __syncthreads();
#pragma unroll
    for (int i = threadIdx.y; i < 32; i += 8) {
        float v = t[threadIdx.x][i];  // = W[by+tx][bx+i]
        Th[(size_t)(bx + i) * 1024 + by + threadIdx.x] = __float2half_rn(v);
    }
}

// ---------------- input split: fp32 -> fp16 hi/lo ----------------
__global__ void __launch_bounds__(256) split_x(const float* __restrict__ x,
                                               __half* __restrict__ xh,
                                               __half* __restrict__ xl) {
    size_t i = ((size_t)blockIdx.x * 256 + threadIdx.x) * 4;
    float4 v = *(const float4*)(x + i);
    split_store_pair(xh, xl, i + 0, v.x, v.y);
    split_store_pair(xh, xl, i + 2, v.z, v.w);
}

// ---------------- loader: one chunk into one stage via cp.async ----------------
DEVFN void load_chunk(unsigned stage, const __half* __restrict__ Ah,
                      const __half* __restrict__ Al, const __half* __restrict__ Bt,
                      int tm, int tn, int c, int tid) {
    const size_t acol = (size_t)c * 64;
#pragma unroll
    for (int i = 0; i < 4; i++) {
        int g = i * 256 + tid;
        int row = g >> 3, k16 = g & 7;
        unsigned dsw = SWZ(row * 128 + k16 * 16);
        size_t soA = (size_t)(tm * 128 + row) * 1024 + acol + k16 * 8;
        CP16(stage + dsw, Ah + soA);
        CP16(stage + 16384 + dsw, Al + soA);
        size_t soB = (size_t)(tn * 128 + row) * 1024 + acol + k16 * 8;
        CP16(stage + 32768 + dsw, Bt + soB);
    }
}

// ---------------- fp16 2-MMA split GEMM: C = (Ah+Al) @ W^T + bias ----------------
// mode 0: write fp32 C. mode 1: ReLU then write split fp16 hi/lo (Ch, Cl).
__global__ void __launch_bounds__(256, 1)
gemm_k(const __half* __restrict__ Ah, const __half* __restrict__ Al,
       const __half* __restrict__ Bt, const float* __restrict__ bias,
       float* __restrict__ Cf, __half* __restrict__ Ch, __half* __restrict__ Cl,
       int mode) {
    extern __shared__ char sm[];
    unsigned sb = smem_u32(sm);
    int tid = threadIdx.x;
    int tn = blockIdx.x, tm = blockIdx.y;
    int lane = tid & 31, wid = tid >> 5;
    int wm = wid & 3, wn = wid >> 2;  // warp grid 4(M) x 2(N), warp tile 32x64

    // ldmatrix per-lane address components
    int a_dr = lane & 15;             // A row within m16 tile
    int a_kb = (lane >> 4) << 4;      // 16B half of k16 block
    int b_dr = (lane & 7) | ((lane >> 4) << 3);
    int b_kb = ((lane >> 3) & 1) << 4;

    unsigned aOff[2], aMsk[2], bOff[4], bMsk[4];
#pragma unroll
    for (int mt = 0; mt < 2; mt++) {
        int row = wm * 32 + mt * 16 + a_dr;
        aOff[mt] = (unsigned)row << 7;
        aMsk[mt] = (unsigned)(row & 7) << 4;
    }
#pragma unroll
    for (int np = 0; np < 4; np++) {
        int row = wn * 64 + np * 16 + b_dr;
        bOff[np] = (unsigned)row << 7;
        bMsk[np] = (unsigned)(row & 7) << 4;
    }

    float acc[2][8][4];
#pragma unroll
    for (int mt = 0; mt < 2; mt++)
#pragma unroll
        for (int nt = 0; nt < 8; nt++)
#pragma unroll
            for (int i = 0; i < 4; i++) acc[mt][nt][i] = 0.f;

    load_chunk(sb + 0 * STAGE, Ah, Al, Bt, tm, tn, 0, tid);
    cpcommit();
    load_chunk(sb + 1 * STAGE, Ah, Al, Bt, tm, tn, 1, tid);
    cpcommit();

    int sidx = 0;  // stage index of chunk c
    for (int c = 0; c < NCHUNK; c++) {
        if (c + 2 < NCHUNK) cpwait<1>(); else cpwait<0>();
        __syncthreads();
        if (c + 2 < NCHUNK) {
            int ns = sidx + 2; if (ns >= NSTAGE) ns -= NSTAGE;
            load_chunk(sb + (unsigned)ns * STAGE, Ah, Al, Bt, tm, tn, c + 2, tid);
            cpcommit();
        }
        unsigned stage = sb + (unsigned)sidx * STAGE;

#pragma unroll
        for (int kk = 0; kk < 4; kk++) {
            unsigned ah[2][4], al[2][4], b[8][2];
            unsigned colA = kk * 32 + a_kb;
            unsigned colB = kk * 32 + b_kb;
#pragma unroll
            for (int mt = 0; mt < 2; mt++) {
                unsigned ad = stage + aOff[mt] + (colA ^ aMsk[mt]);
                LDSM4(ah[mt], ad);
                LDSM4(al[mt], ad + 16384);
            }
#pragma unroll
            for (int np = 0; np < 4; np++) {
                unsigned bd = stage + 32768 + bOff[np] + (colB ^ bMsk[np]);
                unsigned r[4];
                LDSM4(r, bd);
                b[np * 2][0] = r[0]; b[np * 2][1] = r[1];
                b[np * 2 + 1][0] = r[2]; b[np * 2 + 1][1] = r[3];
            }
#pragma unroll
            for (int mt = 0; mt < 2; mt++)
#pragma unroll
                for (int nt = 0; nt < 8; nt++) {
                    MMA16816(acc[mt][nt], ah[mt], b[nt][0], b[nt][1]);
                    MMA16816(acc[mt][nt], al[mt], b[nt][0], b[nt][1]);
                }
        }
        if (++sidx >= NSTAGE) sidx = 0;
    }

    // ---- epilogue ----
#pragma unroll
    for (int nt = 0; nt < 8; nt++) {
        int n = tn * 128 + wn * 64 + nt * 8 + (lane & 3) * 2;
        float b0 = bias[n], b1 = bias[n + 1];
#pragma unroll
        for (int mt = 0; mt < 2; mt++) {
            int r0 = tm * 128 + wm * 32 + mt * 16 + (lane >> 2);
            float v00 = acc[mt][nt][0] + b0, v01 = acc[mt][nt][1] + b1;
            float v10 = acc[mt][nt][2] + b0, v11 = acc[mt][nt][3] + b1;
            if (mode == 0) {
                *(float2*)(Cf + (size_t)r0 * Nc + n) = make_float2(v00, v01);
                *(float2*)(Cf + (size_t)(r0 + 8) * Nc + n) = make_float2(v10, v11);
            } else {
                v00 = fmaxf(v00, 0.f); v01 = fmaxf(v01, 0.f);
                v10 = fmaxf(v10, 0.f); v11 = fmaxf(v11, 0.f);
                split_store_pair(Ch, Cl, (size_t)r0 * Nc + n, v00, v01);
                split_store_pair(Ch, Cl, (size_t)(r0 + 8) * Nc + n, v10, v11);
            }
        }
    }
}

// ---------------- per-token 8x8 attention (one block per token) ----------------
__global__ void __launch_bounds__(128) attn_k(const float* __restrict__ q,
                                              const float* __restrict__ k,
                                              const float* __restrict__ v,
                                              __half* __restrict__ aoh,
                                              __half* __restrict__ aol,
                                              float* __restrict__ aw) {
    constexpr int PS = 136;  // padded row stride
    __shared__ float sQ[8 * PS], sK[8 * PS], sV[8 * PS], sS[64];
    int tok = blockIdx.x, t = threadIdx.x;
    const float* qp = q + (size_t)tok * 1024;
    const float* kp = k + (size_t)tok * 1024;
    const float* vp = v + (size_t)tok * 1024;
#pragma unroll
    for (int i = 0; i < 2; i++) {
        int e = (i * 128 + t) * 4;
        int h = e >> 7, d = e & 127;
        *(float4*)&sQ[h * PS + d] = *(const float4*)(qp + e);
        *(float4*)&sK[h * PS + d] = *(const float4*)(kp + e);
        *(float4*)&sV[h * PS + d] = *(const float4*)(vp + e);
    }
    __syncthreads();
    if (t < 64) {
        int h = t >> 3, tt = t & 7;
        float s = 0.f;
#pragma unroll 16
        for (int i = 0; i < 128; i++) s += sQ[h * PS + i] * sK[tt * PS + i];
        sS[t] = s * 0.08838834764831845f;  // 1/sqrt(128)
    }
    __syncthreads();
    if (t < 8) {
        float m = -1e30f;
#pragma unroll
        for (int j = 0; j < 8; j++) m = fmaxf(m, sS[t * 8 + j]);
        float e[8], sum = 0.f;
#pragma unroll
        for (int j = 0; j < 8; j++) { e[j] = expf(sS[t * 8 + j] - m); sum += e[j]; }
        float inv = 1.f / sum;
#pragma unroll
        for (int j = 0; j < 8; j++) {
            float w = e[j] * inv;
            sS[t * 8 + j] = w;
            aw[(size_t)tok * 64 + t * 8 + j] = w;
        }
    }
    __syncthreads();
    int h = t >> 4, d0 = (t & 15) * 8;
    float o[8];
#pragma unroll
    for (int j = 0; j < 8; j++) o[j] = 0.f;
#pragma unroll
    for (int tt = 0; tt < 8; tt++) {
        float w = sS[h * 8 + tt];
#pragma unroll
        for (int j = 0; j < 8; j++) o[j] += w * sV[tt * PS + d0 + j];
    }
    size_t base = (size_t)tok * 1024 + h * 128 + d0;
#pragma unroll
    for (int j = 0; j < 4; j++)
        split_store_pair(aoh, aol, base + 2 * j, o[2 * j], o[2 * j + 1]);
}

// ---------------- launch ----------------
extern "C" void kernel_launch(void* const* d_in, const int* in_sizes, int n_in,
                              void* d_out, int out_size) {
    (void)in_sizes; (void)n_in;
    const float* x  = (const float*)d_in[0];
    const float* Wq = (const float*)d_in[1];
    const float* bq = (const float*)d_in[2];
    const float* Wk = (const float*)d_in[3];
    const float* bk = (const float*)d_in[4];
    const float* Wv = (const float*)d_in[5];
    const float* bv = (const float*)d_in[6];
    const float* W1 = (const float*)d_in[7];
    const float* b1 = (const float*)d_in[8];
    const float* W2 = (const float*)d_in[9];
    const float* b2 = (const float*)d_in[10];

    float *q, *k, *v, *awf;
    __half *xh, *xl, *aoh, *aol, *hh, *hl, *wt;
    cudaGetSymbolAddress((void**)&q, g_q);
    cudaGetSymbolAddress((void**)&k, g_k);
    cudaGetSymbolAddress((void**)&v, g_v);
    cudaGetSymbolAddress((void**)&xh, g_xh);
    cudaGetSymbolAddress((void**)&xl, g_xl);
    cudaGetSymbolAddress((void**)&aoh, g_aoh);
    cudaGetSymbolAddress((void**)&aol, g_aol);
    cudaGetSymbolAddress((void**)&hh, g_hh);
    cudaGetSymbolAddress((void**)&hl, g_hl);
    cudaGetSymbolAddress((void**)&wt, g_wt);
    cudaGetSymbolAddress((void**)&awf, g_awf);

    cudaFuncSetAttribute(gemm_k, cudaFuncAttributeMaxDynamicSharedMemorySize,
                         SMEM_BYTES);

    // launches #1,#2: input split (two halves so launch #6 = gemm_k for ncu -s 5)
    split_x<<<8192, 256>>>(x, xh, xl);
    split_x<<<8192, 256>>>(x + 8388608, xh + 8388608, xl + 8388608);
    // launch #3: fused weight prep (slots: 0=Wq 1=Wk 2=Wv 3=W1 4=W2)
    prep_all<<<dim3(32, 32, 5), dim3(32, 8)>>>(Wq, Wk, Wv, W1, W2, wt);

    const long long FF = (long long)MTOT * Dc;  // 16777216
    const long long AW = (long long)MTOT * 64;  // 1048576
    float* out_ff = (float*)d_out;
    float* aw = ((long long)out_size >= FF + AW) ? (out_ff + FF) : awf;

    dim3 gg(Nc / 128, MTOT / 128);  // (8, 128)
    gemm_k<<<gg, 256, SMEM_BYTES>>>(xh, xl, wt + 0u * 1048576, bq, q, nullptr,
                                    nullptr, 0);                       // #4
    gemm_k<<<gg, 256, SMEM_BYTES>>>(xh, xl, wt + 1u * 1048576, bk, k, nullptr,
                                    nullptr, 0);                       // #5
    gemm_k<<<gg, 256, SMEM_BYTES>>>(xh, xl, wt + 2u * 1048576, bv, v, nullptr,
                                    nullptr, 0);                       // #6 (profiled)
    attn_k<<<MTOT, 128>>>(q, k, v, aoh, aol, aw);                      // #7
    gemm_k<<<gg, 256, SMEM_BYTES>>>(aoh, aol, wt + 3u * 1048576, b1, nullptr, hh,
                                    hl, 1);                            // #8
    gemm_k<<<gg, 256, SMEM_BYTES>>>(hh, hl, wt + 4u * 1048576, b2, out_ff, nullptr,
                                    nullptr, 0);                       // #9
}

// round 16
// speedup vs baseline: 2.0242x; 1.5329x over previous
#include <cuda_runtime.h>
#include <cuda_fp16.h>
#include <cstdint>

// ---------------- problem constants ----------------
constexpr int Bc = 4, Sc = 4096, Dc = 1024;
constexpr int MTOT = Bc * Sc;   // 16384 rows
constexpr int Kc = 1024, Nc = 1024;
constexpr int NCHUNK = 16;      // K chunks of 64
constexpr int NSTAGE = 4;
constexpr int STAGE = 32768;    // {A 16K, B 16K}
constexpr int SMEM_BYTES = NSTAGE * STAGE;  // 128 KB

// ---------------- device scratch (no allocations allowed) ----------------
__device__ float g_q[(size_t)MTOT * Dc];
__device__ float g_k[(size_t)MTOT * Dc];
__device__ float g_v[(size_t)MTOT * Dc];
__device__ __half g_xh[(size_t)MTOT * Dc];   // fp16 input x
__device__ __half g_aoh[(size_t)MTOT * Dc];  // fp16 attn output
__device__ __half g_hh[(size_t)MTOT * Dc];   // fp16 hidden (post-ReLU)
__device__ __half g_wt[5u * 1024 * 1024];    // transposed weights, fp16
__device__ float g_awf[(size_t)MTOT * 64];   // attn_weights fallback sink

// ---------------- portable PTX helpers (NO 'a'-gated instructions) ----------------
#define DEVFN __device__ __forceinline__

DEVFN unsigned smem_u32(const void* p) {
    unsigned a;
    asm("{ .reg .u64 t; cvta.to.shared.u64 t, %1; cvt.u32.u64 %0, t; }" : "=r"(a) : "l"(p));
    return a;
}

#define CP16(dst, src)                                                       \
    asm volatile("cp.async.cg.shared.global [%0], [%1], 16;" ::"r"(dst),     \
                 "l"(src) : "memory")

DEVFN void cpcommit() { asm volatile("cp.async.commit_group;" ::: "memory"); }

template <int N>
DEVFN void cpwait() { asm volatile("cp.async.wait_group %0;" ::"n"(N) : "memory"); }

#define LDSM4(r, addr)                                                       \
    asm volatile("ldmatrix.sync.aligned.m8n8.x4.shared.b16 {%0,%1,%2,%3}, [%4];" \
                 : "=r"((r)[0]), "=r"((r)[1]), "=r"((r)[2]), "=r"((r)[3])    \
                 : "r"(addr))

#define MMA16816(acc, a, b0v, b1v)                                           \
    asm volatile("mma.sync.aligned.m16n8k16.row.col.f32.f16.f16.f32 "       \
                 "{%0,%1,%2,%3}, {%4,%5,%6,%7}, {%8,%9}, {%0,%1,%2,%3};"    \
                 : "+f"((acc)[0]), "+f"((acc)[1]), "+f"((acc)[2]), "+f"((acc)[3]) \
                 : "r"((a)[0]), "r"((a)[1]), "r"((a)[2]), "r"((a)[3]),       \
                   "r"(b0v), "r"(b1v))

#define SWZ(o) ((unsigned)(o) ^ ((((unsigned)(o)) >> 3) & 0x70u))

DEVFN void h2store(__half* H, size_t off, float v0, float v1) {
    *(__half2*)(H + off) = __floats2half2_rn(v0, v1);
}

// ---------------- weight prep (fused): transpose [K,N] fp32 -> [N,K] fp16 ----------------
__global__ void prep_all(const float* __restrict__ W0, const float* __restrict__ W1,
                         const float* __restrict__ W2, const float* __restrict__ W3,
                         const float* __restrict__ W4, __half* __restrict__ T) {
    __shared__ float t[32][33];
    const float* Ws[5] = {W0, W1, W2, W3, W4};
    const float* W = Ws[blockIdx.z];
    __half* Th = T + (size_t)blockIdx.z * 1048576;
    int bx = blockIdx.x * 32, by = blockIdx.y * 32;
#pragma unroll
    for (int i = threadIdx.y; i < 32; i += 8)
        t[i][threadIdx.x] = W[(size_t)(by + i) * 1024 + bx + threadIdx.x];
    __syncthreads();
#pragma unroll
    for (int i = threadIdx.y; i < 32; i += 8) {
        float v = t[threadIdx.x][i];  // = W[by+tx][bx+i]
        Th[(size_t)(bx + i) * 1024 + by + threadIdx.x] = __float2half_rn(v);
    }
}

// ---------------- input convert: fp32 -> fp16 ----------------
__global__ void __launch_bounds__(256) split_x(const float* __restrict__ x,
                                               __half* __restrict__ xh) {
    size_t i = ((size_t)blockIdx.x * 256 + threadIdx.x) * 4;
    float4 v = *(const float4*)(x + i);
    h2store(xh, i + 0, v.x, v.y);
    h2store(xh, i + 2, v.z, v.w);
}

// ---------------- loader: one chunk (A 16K + B 16K) via cp.async ----------------
DEVFN void load_chunk(unsigned stage, const __half* __restrict__ Ah,
                      const __half* __restrict__ Bt, int tm, int tn, int c,
                      int tid) {
    const size_t acol = (size_t)c * 64;
#pragma unroll
    for (int i = 0; i < 4; i++) {
        int g = i * 256 + tid;
        int row = g >> 3, k16 = g & 7;
        unsigned dsw = SWZ(row * 128 + k16 * 16);
        CP16(stage + dsw, Ah + (size_t)(tm * 128 + row) * 1024 + acol + k16 * 8);
        CP16(stage + 16384 + dsw,
             Bt + (size_t)(tn * 128 + row) * 1024 + acol + k16 * 8);
    }
}

// ---------------- single-fp16 HMMA GEMM body: C = A @ W^T + bias ----------------
// mode 0: write fp32 C. mode 1: ReLU then write fp16 Ch.
DEVFN void gemm_body(const __half* __restrict__ Ah, const __half* __restrict__ Bt,
                     const float* __restrict__ bias, float* __restrict__ Cf,
                     __half* __restrict__ Ch, int mode, int tm, int tn) {
    extern __shared__ char sm[];
    unsigned sb = smem_u32(sm);
    int tid = threadIdx.x;
    int lane = tid & 31, wid = tid >> 5;
    int wm = wid & 3, wn = wid >> 2;  // warp grid 4(M) x 2(N), warp tile 32x64

    // ldmatrix per-lane address components
    int a_dr = lane & 15;
    int a_kb = (lane >> 4) << 4;
    int b_dr = (lane & 7) | ((lane >> 4) << 3);
    int b_kb = ((lane >> 3) & 1) << 4;

    unsigned aOff[2], aMsk[2], bOff[4], bMsk[4];
#pragma unroll
    for (int mt = 0; mt < 2; mt++) {
        int row = wm * 32 + mt * 16 + a_dr;
        aOff[mt] = (unsigned)row << 7;
        aMsk[mt] = (unsigned)(row & 7) << 4;
    }
#pragma unroll
    for (int np = 0; np < 4; np++) {
        int row = wn * 64 + np * 16 + b_dr;
        bOff[np] = (unsigned)row << 7;
        bMsk[np] = (unsigned)(row & 7) << 4;
    }

    float acc[2][8][4];
#pragma unroll
    for (int mt = 0; mt < 2; mt++)
#pragma unroll
        for (int nt = 0; nt < 8; nt++)
#pragma unroll
            for (int i = 0; i < 4; i++) acc[mt][nt][i] = 0.f;

    // prologue: 3 stages in flight
#pragma unroll
    for (int p = 0; p < 3; p++) {
        load_chunk(sb + (unsigned)p * STAGE, Ah, Bt, tm, tn, p, tid);
        cpcommit();
    }

    for (int c = 0; c < NCHUNK; c++) {
        if (c < NCHUNK - 2) cpwait<2>();
        else if (c == NCHUNK - 2) cpwait<1>();
        else cpwait<0>();
        __syncthreads();
        if (c + 3 < NCHUNK) {
            load_chunk(sb + (unsigned)((c + 3) & 3) * STAGE, Ah, Bt, tm, tn, c + 3,
                       tid);
            cpcommit();
        }
        unsigned stage = sb + (unsigned)(c & 3) * STAGE;

#pragma unroll
        for (int kk = 0; kk < 4; kk++) {
            unsigned ah[2][4], b[8][2];
            unsigned colA = kk * 32 + a_kb;
            unsigned colB = kk * 32 + b_kb;
#pragma unroll
            for (int mt = 0; mt < 2; mt++)
                LDSM4(ah[mt], stage + aOff[mt] + (colA ^ aMsk[mt]));
#pragma unroll
            for (int np = 0; np < 4; np++) {
                unsigned r[4];
                LDSM4(r, stage + 16384 + bOff[np] + (colB ^ bMsk[np]));
                b[np * 2][0] = r[0]; b[np * 2][1] = r[1];
                b[np * 2 + 1][0] = r[2]; b[np * 2 + 1][1] = r[3];
            }
#pragma unroll
            for (int mt = 0; mt < 2; mt++)
#pragma unroll
                for (int nt = 0; nt < 8; nt++)
                    MMA16816(acc[mt][nt], ah[mt], b[nt][0], b[nt][1]);
        }
    }

    // ---- epilogue ----
#pragma unroll
    for (int nt = 0; nt < 8; nt++) {
        int n = tn * 128 + wn * 64 + nt * 8 + (lane & 3) * 2;
        float b0 = bias[n], b1 = bias[n + 1];
#pragma unroll
        for (int mt = 0; mt < 2; mt++) {
            int r0 = tm * 128 + wm * 32 + mt * 16 + (lane >> 2);
            float v00 = acc[mt][nt][0] + b0, v01 = acc[mt][nt][1] + b1;
            float v10 = acc[mt][nt][2] + b0, v11 = acc[mt][nt][3] + b1;
            if (mode == 0) {
                *(float2*)(Cf + (size_t)r0 * Nc + n) = make_float2(v00, v01);
                *(float2*)(Cf + (size_t)(r0 + 8) * Nc + n) = make_float2(v10, v11);
            } else {
                h2store(Ch, (size_t)r0 * Nc + n, fmaxf(v00, 0.f), fmaxf(v01, 0.f));
                h2store(Ch, (size_t)(r0 + 8) * Nc + n, fmaxf(v10, 0.f),
                        fmaxf(v11, 0.f));
            }
        }
    }
}

__global__ void __launch_bounds__(256, 1)
gemm_k(const __half* __restrict__ Ah, const __half* __restrict__ Bt,
       const float* __restrict__ bias, float* __restrict__ Cf,
       __half* __restrict__ Ch, int mode) {
    gemm_body(Ah, Bt, bias, Cf, Ch, mode, blockIdx.y, blockIdx.x);
}

// fused Q/K/V projections: blockIdx.z selects weight/bias/output slot
__global__ void __launch_bounds__(256, 1)
qkv_k(const __half* __restrict__ Ah, const __half* __restrict__ Wt,
      const float* __restrict__ bq, const float* __restrict__ bk,
      const float* __restrict__ bv, float* __restrict__ q, float* __restrict__ k,
      float* __restrict__ v) {
    int z = blockIdx.z;
    const float* bias = (z == 0) ? bq : (z == 1) ? bk : bv;
    float* C = (z == 0) ? q : (z == 1) ? k : v;
    gemm_body(Ah, Wt + (size_t)z * 1048576, bias, C, nullptr, 0, blockIdx.y,
              blockIdx.x);
}

// ---------------- per-token 8x8 attention (one block per token) ----------------
__global__ void __launch_bounds__(128) attn_k(const float* __restrict__ q,
                                              const float* __restrict__ k,
                                              const float* __restrict__ v,
                                              __half* __restrict__ aoh,
                                              float* __restrict__ aw) {
    constexpr int PS = 136;  // padded row stride
    __shared__ float sQ[8 * PS], sK[8 * PS], sV[8 * PS], sS[64];
    int tok = blockIdx.x, t = threadIdx.x;
    const float* qp = q + (size_t)tok * 1024;
    const float* kp = k + (size_t)tok * 1024;
    const float* vp = v + (size_t)tok * 1024;
#pragma unroll
    for (int i = 0; i < 2; i++) {
        int e = (i * 128 + t) * 4;
        int h = e >> 7, d = e & 127;
        *(float4*)&sQ[h * PS + d] = *(const float4*)(qp + e);
        *(float4*)&sK[h * PS + d] = *(const float4*)(kp + e);
        *(float4*)&sV[h * PS + d] = *(const float4*)(vp + e);
    }
    __syncthreads();
    if (t < 64) {
        int h = t >> 3, tt = t & 7;
        float s = 0.f;
#pragma unroll 16
        for (int i = 0; i < 128; i++) s += sQ[h * PS + i] * sK[tt * PS + i];
        sS[t] = s * 0.08838834764831845f;  // 1/sqrt(128)
    }
    __syncthreads();
    if (t < 8) {
        float m = -1e30f;
#pragma unroll
        for (int j = 0; j < 8; j++) m = fmaxf(m, sS[t * 8 + j]);
        float e[8], sum = 0.f;
#pragma unroll
        for (int j = 0; j < 8; j++) { e[j] = expf(sS[t * 8 + j] - m); sum += e[j]; }
        float inv = 1.f / sum;
#pragma unroll
        for (int j = 0; j < 8; j++) {
            float w = e[j] * inv;
            sS[t * 8 + j] = w;
            aw[(size_t)tok * 64 + t * 8 + j] = w;
        }
    }
    __syncthreads();
    int h = t >> 4, d0 = (t & 15) * 8;
    float o[8];
#pragma unroll
    for (int j = 0; j < 8; j++) o[j] = 0.f;
#pragma unroll
    for (int tt = 0; tt < 8; tt++) {
        float w = sS[h * 8 + tt];
#pragma unroll
        for (int j = 0; j < 8; j++) o[j] += w * sV[tt * PS + d0 + j];
    }
    size_t base = (size_t)tok * 1024 + h * 128 + d0;
#pragma unroll
    for (int j = 0; j < 4; j++) h2store(aoh, base + 2 * j, o[2 * j], o[2 * j + 1]);
}

// ---------------- launch ----------------
extern "C" void kernel_launch(void* const* d_in, const int* in_sizes, int n_in,
                              void* d_out, int out_size) {
    (void)in_sizes; (void)n_in;
    const float* x  = (const float*)d_in[0];
    const float* Wq = (const float*)d_in[1];
    const float* bq = (const float*)d_in[2];
    const float* Wk = (const float*)d_in[3];
    const float* bk = (const float*)d_in[4];
    const float* Wv = (const float*)d_in[5];
    const float* bv = (const float*)d_in[6];
    const float* W1 = (const float*)d_in[7];
    const float* b1 = (const float*)d_in[8];
    const float* W2 = (const float*)d_in[9];
    const float* b2 = (const float*)d_in[10];

    float *q, *k, *v, *awf;
    __half *xh, *aoh, *hh, *wt;
    cudaGetSymbolAddress((void**)&q, g_q);
    cudaGetSymbolAddress((void**)&k, g_k);
    cudaGetSymbolAddress((void**)&v, g_v);
    cudaGetSymbolAddress((void**)&xh, g_xh);
    cudaGetSymbolAddress((void**)&aoh, g_aoh);
    cudaGetSymbolAddress((void**)&hh, g_hh);
    cudaGetSymbolAddress((void**)&wt, g_wt);
    cudaGetSymbolAddress((void**)&awf, g_awf);

    cudaFuncSetAttribute(gemm_k, cudaFuncAttributeMaxDynamicSharedMemorySize,
                         SMEM_BYTES);
    cudaFuncSetAttribute(qkv_k, cudaFuncAttributeMaxDynamicSharedMemorySize,
                         SMEM_BYTES);

    // #1: input fp16 convert   #2: fused weight prep (0=Wq 1=Wk 2=Wv 3=W1 4=W2)
    split_x<<<MTOT * Dc / 1024, 256>>>(x, xh);
    prep_all<<<dim3(32, 32, 5), dim3(32, 8)>>>(Wq, Wk, Wv, W1, W2, wt);

    const long long FF = (long long)MTOT * Dc;  // 16777216
    const long long AW = (long long)MTOT * 64;  // 1048576
    float* out_ff = (float*)d_out;
    float* aw = ((long long)out_size >= FF + AW) ? (out_ff + FF) : awf;

    dim3 gq(Nc / 128, MTOT / 128, 3);  // (8, 128, 3)
    dim3 gg(Nc / 128, MTOT / 128);     // (8, 128)
    qkv_k<<<gq, 256, SMEM_BYTES>>>(xh, wt, bq, bk, bv, q, k, v);        // #3
    attn_k<<<MTOT, 128>>>(q, k, v, aoh, aw);                            // #4
    gemm_k<<<gg, 256, SMEM_BYTES>>>(aoh, wt + 3u * 1048576, b1, nullptr, hh, 1); // #5
    gemm_k<<<gg, 256, SMEM_BYTES>>>(hh, wt + 4u * 1048576, b2, out_ff, nullptr,
                                    0);                                 // #6 (profiled)
}

// round 17
// speedup vs baseline: 2.6007x; 1.2848x over previous
#include <cuda_runtime.h>
#include <cuda_fp16.h>
#include <cstdint>

// ---------------- problem constants ----------------
constexpr int Bc = 4, Sc = 4096, Dc = 1024;
constexpr int MTOT = Bc * Sc;   // 16384 rows
constexpr int Kc = 1024, Nc = 1024;
constexpr int NCHUNK = 16;      // K chunks of 64
constexpr int NSTAGE = 3;
constexpr int STAGE = 32768;    // {A 16K, B 16K}
constexpr int SMEM_BYTES = NSTAGE * STAGE;  // 96 KB -> 2 CTAs/SM

// ---------------- device scratch (no allocations allowed) ----------------
__device__ __half g_qh[(size_t)MTOT * Dc];
__device__ __half g_kh[(size_t)MTOT * Dc];
__device__ __half g_vh[(size_t)MTOT * Dc];
__device__ __half g_xh[(size_t)MTOT * Dc];   // fp16 input x
__device__ __half g_aoh[(size_t)MTOT * Dc];  // fp16 attn output
__device__ __half g_hh[(size_t)MTOT * Dc];   // fp16 hidden (post-ReLU)
__device__ __half g_wt[5u * 1024 * 1024];    // transposed weights, fp16
__device__ float g_awf[(size_t)MTOT * 64];   // attn_weights fallback sink

// ---------------- portable PTX helpers (NO 'a'-gated instructions) ----------------
#define DEVFN __device__ __forceinline__

DEVFN unsigned smem_u32(const void* p) {
    unsigned a;
    asm("{ .reg .u64 t; cvta.to.shared.u64 t, %1; cvt.u32.u64 %0, t; }" : "=r"(a) : "l"(p));
    return a;
}

#define CP16(dst, src)                                                       \
    asm volatile("cp.async.cg.shared.global [%0], [%1], 16;" ::"r"(dst),     \
                 "l"(src) : "memory")

DEVFN void cpcommit() { asm volatile("cp.async.commit_group;" ::: "memory"); }

template <int N>
DEVFN void cpwait() { asm volatile("cp.async.wait_group %0;" ::"n"(N) : "memory"); }

#define LDSM4(r, addr)                                                       \
    asm volatile("ldmatrix.sync.aligned.m8n8.x4.shared.b16 {%0,%1,%2,%3}, [%4];" \
                 : "=r"((r)[0]), "=r"((r)[1]), "=r"((r)[2]), "=r"((r)[3])    \
                 : "r"(addr))

#define MMA16816(acc, a, b0v, b1v)                                           \
    asm volatile("mma.sync.aligned.m16n8k16.row.col.f32.f16.f16.f32 "       \
                 "{%0,%1,%2,%3}, {%4,%5,%6,%7}, {%8,%9}, {%0,%1,%2,%3};"    \
                 : "+f"((acc)[0]), "+f"((acc)[1]), "+f"((acc)[2]), "+f"((acc)[3]) \
                 : "r"((a)[0]), "r"((a)[1]), "r"((a)[2]), "r"((a)[3]),       \
                   "r"(b0v), "r"(b1v))

#define SWZ(o) ((unsigned)(o) ^ ((((unsigned)(o)) >> 3) & 0x70u))

DEVFN void h2store(__half* H, size_t off, float v0, float v1) {
    *(__half2*)(H + off) = __floats2half2_rn(v0, v1);
}

// ---------------- weight prep (fused): transpose [K,N] fp32 -> [N,K] fp16 ----------------
__global__ void prep_all(const float* __restrict__ W0, const float* __restrict__ W1,
                         const float* __restrict__ W2, const float* __restrict__ W3,
                         const float* __restrict__ W4, __half* __restrict__ T) {
    __shared__ float t[32][33];
    const float* Ws[5] = {W0, W1, W2, W3, W4};
    const float* W = Ws[blockIdx.z];
    __half* Th = T + (size_t)blockIdx.z * 1048576;
    int bx = blockIdx.x * 32, by = blockIdx.y * 32;
#pragma unroll
    for (int i = threadIdx.y; i < 32; i += 8)
        t[i][threadIdx.x] = W[(size_t)(by + i) * 1024 + bx + threadIdx.x];
    __syncthreads();
#pragma unroll
    for (int i = threadIdx.y; i < 32; i += 8) {
        float v = t[threadIdx.x][i];  // = W[by+tx][bx+i]
        Th[(size_t)(bx + i) * 1024 + by + threadIdx.x] = __float2half_rn(v);
    }
}

// ---------------- input convert: fp32 -> fp16 ----------------
__global__ void __launch_bounds__(256) split_x(const float* __restrict__ x,
                                               __half* __restrict__ xh) {
    size_t i = ((size_t)blockIdx.x * 256 + threadIdx.x) * 4;
    float4 v = *(const float4*)(x + i);
    h2store(xh, i + 0, v.x, v.y);
    h2store(xh, i + 2, v.z, v.w);
}

// ---------------- loader: one chunk (A 16K + B 16K) via cp.async ----------------
DEVFN void load_chunk(unsigned stage, const __half* __restrict__ Ah,
                      const __half* __restrict__ Bt, int tm, int tn, int c,
                      int tid) {
    const size_t acol = (size_t)c * 64;
#pragma unroll
    for (int i = 0; i < 4; i++) {
        int g = i * 256 + tid;
        int row = g >> 3, k16 = g & 7;
        unsigned dsw = SWZ(row * 128 + k16 * 16);
        CP16(stage + dsw, Ah + (size_t)(tm * 128 + row) * 1024 + acol + k16 * 8);
        CP16(stage + 16384 + dsw,
             Bt + (size_t)(tn * 128 + row) * 1024 + acol + k16 * 8);
    }
}

// ---------------- single-fp16 HMMA GEMM body: C = A @ W^T + bias ----------------
// mode 0: fp32 out Cf. mode 1: ReLU -> fp16 Ch. mode 2: plain fp16 Ch.
DEVFN void gemm_body(const __half* __restrict__ Ah, const __half* __restrict__ Bt,
                     const float* __restrict__ bias, float* __restrict__ Cf,
                     __half* __restrict__ Ch, int mode, int tm, int tn) {
    extern __shared__ char sm[];
    unsigned sb = smem_u32(sm);
    int tid = threadIdx.x;
    int lane = tid & 31, wid = tid >> 5;
    int wm = wid & 3, wn = wid >> 2;  // warp grid 4(M) x 2(N), warp tile 32x64

    // ldmatrix per-lane address components
    int a_dr = lane & 15;
    int a_kb = (lane >> 4) << 4;
    int b_dr = (lane & 7) | ((lane >> 4) << 3);
    int b_kb = ((lane >> 3) & 1) << 4;

    unsigned aOff[2], aMsk[2], bOff[4], bMsk[4];
#pragma unroll
    for (int mt = 0; mt < 2; mt++) {
        int row = wm * 32 + mt * 16 + a_dr;
        aOff[mt] = (unsigned)row << 7;
        aMsk[mt] = (unsigned)(row & 7) << 4;
    }
#pragma unroll
    for (int np = 0; np < 4; np++) {
        int row = wn * 64 + np * 16 + b_dr;
        bOff[np] = (unsigned)row << 7;
        bMsk[np] = (unsigned)(row & 7) << 4;
    }

    float acc[2][8][4];
#pragma unroll
    for (int mt = 0; mt < 2; mt++)
#pragma unroll
        for (int nt = 0; nt < 8; nt++)
#pragma unroll
            for (int i = 0; i < 4; i++) acc[mt][nt][i] = 0.f;

    // prologue: 2 stages in flight
#pragma unroll
    for (int p = 0; p < 2; p++) {
        load_chunk(sb + (unsigned)p * STAGE, Ah, Bt, tm, tn, p, tid);
        cpcommit();
    }

    int sidx = 0;
    for (int c = 0; c < NCHUNK; c++) {
        if (c + 1 < NCHUNK) cpwait<1>(); else cpwait<0>();
        __syncthreads();
        if (c + 2 < NCHUNK) {
            int ns = sidx + 2; if (ns >= NSTAGE) ns -= NSTAGE;
            load_chunk(sb + (unsigned)ns * STAGE, Ah, Bt, tm, tn, c + 2, tid);
            cpcommit();
        }
        unsigned stage = sb + (unsigned)sidx * STAGE;

#pragma unroll
        for (int kk = 0; kk < 4; kk++) {
            unsigned ah[2][4], b[8][2];
            unsigned colA = kk * 32 + a_kb;
            unsigned colB = kk * 32 + b_kb;
#pragma unroll
            for (int mt = 0; mt < 2; mt++)
                LDSM4(ah[mt], stage + aOff[mt] + (colA ^ aMsk[mt]));
#pragma unroll
            for (int np = 0; np < 4; np++) {
                unsigned r[4];
                LDSM4(r, stage + 16384 + bOff[np] + (colB ^ bMsk[np]));
                b[np * 2][0] = r[0]; b[np * 2][1] = r[1];
                b[np * 2 + 1][0] = r[2]; b[np * 2 + 1][1] = r[3];
            }
#pragma unroll
            for (int mt = 0; mt < 2; mt++)
#pragma unroll
                for (int nt = 0; nt < 8; nt++)
                    MMA16816(acc[mt][nt], ah[mt], b[nt][0], b[nt][1]);
        }
        if (++sidx >= NSTAGE) sidx = 0;
    }

    // ---- epilogue ----
#pragma unroll
    for (int nt = 0; nt < 8; nt++) {
        int n = tn * 128 + wn * 64 + nt * 8 + (lane & 3) * 2;
        float b0 = bias[n], b1 = bias[n + 1];
#pragma unroll
        for (int mt = 0; mt < 2; mt++) {
            int r0 = tm * 128 + wm * 32 + mt * 16 + (lane >> 2);
            float v00 = acc[mt][nt][0] + b0, v01 = acc[mt][nt][1] + b1;
            float v10 = acc[mt][nt][2] + b0, v11 = acc[mt][nt][3] + b1;
            if (mode == 0) {
                *(float2*)(Cf + (size_t)r0 * Nc + n) = make_float2(v00, v01);
                *(float2*)(Cf + (size_t)(r0 + 8) * Nc + n) = make_float2(v10, v11);
            } else {
                if (mode == 1) {
                    v00 = fmaxf(v00, 0.f); v01 = fmaxf(v01, 0.f);
                    v10 = fmaxf(v10, 0.f); v11 = fmaxf(v11, 0.f);
                }
                h2store(Ch, (size_t)r0 * Nc + n, v00, v01);
                h2store(Ch, (size_t)(r0 + 8) * Nc + n, v10, v11);
            }
        }
    }
}

__global__ void __launch_bounds__(256, 2)
gemm_k(const __half* __restrict__ Ah, const __half* __restrict__ Bt,
       const float* __restrict__ bias, float* __restrict__ Cf,
       __half* __restrict__ Ch, int mode) {
    gemm_body(Ah, Bt, bias, Cf, Ch, mode, blockIdx.y, blockIdx.x);
}

// fused Q/K/V projections: blockIdx.z selects weight/bias/output slot (fp16 out)
__global__ void __launch_bounds__(256, 2)
qkv_k(const __half* __restrict__ Ah, const __half* __restrict__ Wt,
      const float* __restrict__ bq, const float* __restrict__ bk,
      const float* __restrict__ bv, __half* __restrict__ q, __half* __restrict__ k,
      __half* __restrict__ v) {
    int z = blockIdx.z;
    const float* bias = (z == 0) ? bq : (z == 1) ? bk : bv;
    __half* C = (z == 0) ? q : (z == 1) ? k : v;
    gemm_body(Ah, Wt + (size_t)z * 1048576, bias, nullptr, C, 2, blockIdx.y,
              blockIdx.x);
}

// ---------------- per-token 8x8 attention (one block per token, fp16 I/O) ----------------
__global__ void __launch_bounds__(128) attn_k(const __half* __restrict__ q,
                                              const __half* __restrict__ k,
                                              const __half* __restrict__ v,
                                              __half* __restrict__ aoh,
                                              float* __restrict__ aw) {
    constexpr int PS = 136;  // padded row stride (halves)
    __shared__ __half sQ[8 * PS], sK[8 * PS], sV[8 * PS];
    __shared__ float sS[64];
    int tok = blockIdx.x, t = threadIdx.x;
    const __half* qp = q + (size_t)tok * 1024;
    const __half* kp = k + (size_t)tok * 1024;
    const __half* vp = v + (size_t)tok * 1024;
    {
        // 128 threads x 8 halves = 1024 halves per tensor
        int row = t >> 4, col = (t & 15) * 8;
        *(uint4*)&sQ[row * PS + col] = *(const uint4*)(qp + row * 128 + col);
        *(uint4*)&sK[row * PS + col] = *(const uint4*)(kp + row * 128 + col);
        *(uint4*)&sV[row * PS + col] = *(const uint4*)(vp + row * 128 + col);
    }
    __syncthreads();
    if (t < 64) {
        int h = t >> 3, tt = t & 7;
        float s = 0.f;
        const __half2* qr = (const __half2*)&sQ[h * PS];
        const __half2* kr = (const __half2*)&sK[tt * PS];
#pragma unroll 16
        for (int i = 0; i < 64; i++) {
            float2 a = __half22float2(qr[i]);
            float2 b = __half22float2(kr[i]);
            s += a.x * b.x + a.y * b.y;
        }
        sS[t] = s * 0.08838834764831845f;  // 1/sqrt(128)
    }
    __syncthreads();
    if (t < 8) {
        float m = -1e30f;
#pragma unroll
        for (int j = 0; j < 8; j++) m = fmaxf(m, sS[t * 8 + j]);
        float e[8], sum = 0.f;
#pragma unroll
        for (int j = 0; j < 8; j++) { e[j] = expf(sS[t * 8 + j] - m); sum += e[j]; }
        float inv = 1.f / sum;
#pragma unroll
        for (int j = 0; j < 8; j++) sS[t * 8 + j] = e[j] * inv;
    }
    __syncthreads();
    if (t < 64) aw[(size_t)tok * 64 + t] = sS[t];  // coalesced attn_weights
    int h = t >> 4, d0 = (t & 15) * 8;
    float o[8];
#pragma unroll
    for (int j = 0; j < 8; j++) o[j] = 0.f;
#pragma unroll
    for (int tt = 0; tt < 8; tt++) {
        float w = sS[h * 8 + tt];
        const __half2* vr = (const __half2*)&sV[tt * PS + d0];
#pragma unroll
        for (int j = 0; j < 4; j++) {
            float2 vv = __half22float2(vr[j]);
            o[2 * j] += w * vv.x;
            o[2 * j + 1] += w * vv.y;
        }
    }
    // pack 8 halves -> one 16B store
    __half2 p0 = __floats2half2_rn(o[0], o[1]), p1 = __floats2half2_rn(o[2], o[3]);
    __half2 p2 = __floats2half2_rn(o[4], o[5]), p3 = __floats2half2_rn(o[6], o[7]);
    uint4 pk;
    pk.x = *(unsigned*)&p0; pk.y = *(unsigned*)&p1;
    pk.z = *(unsigned*)&p2; pk.w = *(unsigned*)&p3;
    *(uint4*)(aoh + (size_t)tok * 1024 + h * 128 + d0) = pk;
}

// ---------------- launch ----------------
extern "C" void kernel_launch(void* const* d_in, const int* in_sizes, int n_in,
                              void* d_out, int out_size) {
    (void)in_sizes; (void)n_in;
    const float* x  = (const float*)d_in[0];
    const float* Wq = (const float*)d_in[1];
    const float* bq = (const float*)d_in[2];
    const float* Wk = (const float*)d_in[3];
    const float* bk = (const float*)d_in[4];
    const float* Wv = (const float*)d_in[5];
    const float* bv = (const float*)d_in[6];
    const float* W1 = (const float*)d_in[7];
    const float* b1 = (const float*)d_in[8];
    const float* W2 = (const float*)d_in[9];
    const float* b2 = (const float*)d_in[10];

    float* awf;
    __half *qh, *kh, *vh, *xh, *aoh, *hh, *wt;
    cudaGetSymbolAddress((void**)&qh, g_qh);
    cudaGetSymbolAddress((void**)&kh, g_kh);
    cudaGetSymbolAddress((void**)&vh, g_vh);
    cudaGetSymbolAddress((void**)&xh, g_xh);
    cudaGetSymbolAddress((void**)&aoh, g_aoh);
    cudaGetSymbolAddress((void**)&hh, g_hh);
    cudaGetSymbolAddress((void**)&wt, g_wt);
    cudaGetSymbolAddress((void**)&awf, g_awf);

    cudaFuncSetAttribute(gemm_k, cudaFuncAttributeMaxDynamicSharedMemorySize,
                         SMEM_BYTES);
    cudaFuncSetAttribute(qkv_k, cudaFuncAttributeMaxDynamicSharedMemorySize,
                         SMEM_BYTES);

    // #1: input fp16 convert   #2: fused weight prep (0=Wq 1=Wk 2=Wv 3=W1 4=W2)
    split_x<<<MTOT * Dc / 1024, 256>>>(x, xh);
    prep_all<<<dim3(32, 32, 5), dim3(32, 8)>>>(Wq, Wk, Wv, W1, W2, wt);

    const long long FF = (long long)MTOT * Dc;  // 16777216
    const long long AW = (long long)MTOT * 64;  // 1048576
    float* out_ff = (float*)d_out;
    float* aw = ((long long)out_size >= FF + AW) ? (out_ff + FF) : awf;

    dim3 gq(Nc / 128, MTOT / 128, 3);  // (8, 128, 3)
    dim3 gg(Nc / 128, MTOT / 128);     // (8, 128)
    qkv_k<<<gq, 256, SMEM_BYTES>>>(xh, wt, bq, bk, bv, qh, kh, vh);     // #3
    attn_k<<<MTOT, 128>>>(qh, kh, vh, aoh, aw);                         // #4
    gemm_k<<<gg, 256, SMEM_BYTES>>>(aoh, wt + 3u * 1048576, b1, nullptr, hh, 1); // #5
    gemm_k<<<gg, 256, SMEM_BYTES>>>(hh, wt + 4u * 1048576, b2, out_ff, nullptr,
                                    0);                                 // #6 (profiled)
}